// round 2
// baseline (speedup 1.0000x reference)
#include <cuda_runtime.h>
#include <cuda_bf16.h>

// ---------------------------------------------------------------------------
// BinaryDenseLayer: out[4096,4096] = x[4096,4096] @ sign(W)[4096,4096] + b
// S = sign(W)^T as bf16 (exact +-1), x split into bf16 hi+lo, two bf16
// mma.sync GEMMs sharing one fp32 accumulator. (tcgen05 unavailable: harness
// PTX target is sm_103 without the 'a' feature suffix.)
// ---------------------------------------------------------------------------

#define DIMM 4096

constexpr int BM = 128;
constexpr int BN = 128;
constexpr int BK = 64;
constexpr int STAGES = 3;
constexpr int KITERS = DIMM / BK;           // 64
constexpr int TILE_BYTES = 128 * 64 * 2;    // 16384 (one 128x64 bf16 tile)
constexpr int STAGE_BYTES = 3 * TILE_BYTES; // Ahi + Alo + B = 49152
constexpr int SMEM_TOTAL = STAGES * STAGE_BYTES;  // 147456

// Scratch (sanctioned: __device__ globals, no allocation)
__device__ __align__(1024) __nv_bfloat16 g_S[(size_t)DIMM * DIMM];    // [N][K] = sign(W)^T
__device__ __align__(1024) __nv_bfloat16 g_xhi[(size_t)DIMM * DIMM];  // [M][K]
__device__ __align__(1024) __nv_bfloat16 g_xlo[(size_t)DIMM * DIMM];  // [M][K]

// ------------------------- helpers -----------------------------------------

__device__ __forceinline__ unsigned smem_u32(const void* p) {
    unsigned a;
    asm("{ .reg .u64 t; cvta.to.shared.u64 t, %1; cvt.u32.u64 %0, t; }" : "=r"(a) : "l"(p));
    return a;
}

__device__ __forceinline__ unsigned sw128(unsigned off) {
    return off ^ ((off >> 3) & 0x70);
}

__device__ __forceinline__ void cp16(unsigned dst, const void* src) {
    asm volatile("cp.async.cg.shared.global [%0], [%1], 16;" ::"r"(dst), "l"(src));
}

__device__ __forceinline__ void ldsm_x4(unsigned& r0, unsigned& r1, unsigned& r2, unsigned& r3,
                                        unsigned addr) {
    asm volatile("ldmatrix.sync.aligned.m8n8.x4.shared.b16 {%0,%1,%2,%3}, [%4];"
                 : "=r"(r0), "=r"(r1), "=r"(r2), "=r"(r3)
                 : "r"(addr));
}

__device__ __forceinline__ void mma16816(float* d, const unsigned* a, const unsigned* b) {
    asm volatile(
        "mma.sync.aligned.m16n8k16.row.col.f32.bf16.bf16.f32 "
        "{%0,%1,%2,%3}, {%4,%5,%6,%7}, {%8,%9}, {%0,%1,%2,%3};"
        : "+f"(d[0]), "+f"(d[1]), "+f"(d[2]), "+f"(d[3])
        : "r"(a[0]), "r"(a[1]), "r"(a[2]), "r"(a[3]), "r"(b[0]), "r"(b[1]));
}

// ------------------------- prep kernels ------------------------------------

// x -> (x_hi, x_lo) bf16 split
__global__ void split_kernel(const float* __restrict__ x) {
    size_t i = ((size_t)blockIdx.x * blockDim.x + threadIdx.x) * 4;
    float4 v = *reinterpret_cast<const float4*>(x + i);
    __nv_bfloat16 h0 = __float2bfloat16(v.x);
    __nv_bfloat16 h1 = __float2bfloat16(v.y);
    __nv_bfloat16 h2 = __float2bfloat16(v.z);
    __nv_bfloat16 h3 = __float2bfloat16(v.w);
    __nv_bfloat16 l0 = __float2bfloat16(v.x - __bfloat162float(h0));
    __nv_bfloat16 l1 = __float2bfloat16(v.y - __bfloat162float(h1));
    __nv_bfloat16 l2 = __float2bfloat16(v.z - __bfloat162float(h2));
    __nv_bfloat16 l3 = __float2bfloat16(v.w - __bfloat162float(h3));
    __nv_bfloat162 p;
    __nv_bfloat162* ph = reinterpret_cast<__nv_bfloat162*>(g_xhi + i);
    __nv_bfloat162* pl = reinterpret_cast<__nv_bfloat162*>(g_xlo + i);
    p.x = h0; p.y = h1; ph[0] = p;
    p.x = h2; p.y = h3; ph[1] = p;
    p.x = l0; p.y = l1; pl[0] = p;
    p.x = l2; p.y = l3; pl[1] = p;
}

// S[n][k] = sign(W[k][n]) as bf16, via 32x32 smem transpose tile
__global__ void signT_kernel(const float* __restrict__ W) {
    __shared__ __nv_bfloat16 t[32][33];
    int nb = blockIdx.x * 32, kb = blockIdx.y * 32;
    int tx = threadIdx.x, ty = threadIdx.y;
#pragma unroll
    for (int i = 0; i < 4; i++) {
        float w = W[(size_t)(kb + ty + i * 8) * DIMM + nb + tx];
        t[ty + i * 8][tx] = __float2bfloat16(w > 0.f ? 1.f : (w < 0.f ? -1.f : 0.f));
    }
    __syncthreads();
#pragma unroll
    for (int i = 0; i < 4; i++) {
        g_S[(size_t)(nb + ty + i * 8) * DIMM + kb + tx] = t[tx][ty + i * 8];
    }
}

// ------------------------- GEMM kernel -------------------------------------
// grid = 32*32 = 1024 CTAs; block = 256 threads (8 warps, 4m x 2n).
// Warp tile 32(m) x 64(n); mma.sync m16n8k16; cp.async 3-stage pipeline.
__global__ void __launch_bounds__(256, 1)
bgemm_kernel(const float* __restrict__ bias, float* __restrict__ out) {
    extern __shared__ char smem[];
    unsigned sb = smem_u32(smem);
    int tid = threadIdx.x;
    int wid = tid >> 5, lane = tid & 31;
    int wm = wid & 3;   // warp m index (0..3)
    int wn = wid >> 2;  // warp n index (0..1)
    int m_base = (blockIdx.x & 31) * BM;
    int n_base = (blockIdx.x >> 5) * BN;

    // per-thread cp.async offsets: 4 passes per 16KB tile
    // pass p, thread tid -> element idx = p*256+tid; row = idx/8, colb = (idx%8)*16
    unsigned s_off[4];
    size_t g_off[4];
#pragma unroll
    for (int p = 0; p < 4; p++) {
        int idx = p * 256 + tid;
        int row = idx >> 3;
        int colb = (idx & 7) * 16;
        s_off[p] = sw128((unsigned)(row * 128 + colb));
        g_off[p] = (size_t)row * (DIMM * 2) + colb;
    }
    const char* gAh = reinterpret_cast<const char*>(g_xhi) + (size_t)m_base * (DIMM * 2);
    const char* gAl = reinterpret_cast<const char*>(g_xlo) + (size_t)m_base * (DIMM * 2);
    const char* gB  = reinterpret_cast<const char*>(g_S)   + (size_t)n_base * (DIMM * 2);

#define LOAD_STAGE(s, kit)                                                     \
    do {                                                                       \
        unsigned base = sb + (s) * STAGE_BYTES;                                \
        size_t kb = (size_t)(kit) * (BK * 2);                                  \
        _Pragma("unroll") for (int p = 0; p < 4; p++) {                        \
            cp16(base + s_off[p], gAh + kb + g_off[p]);                        \
            cp16(base + TILE_BYTES + s_off[p], gAl + kb + g_off[p]);           \
            cp16(base + 2 * TILE_BYTES + s_off[p], gB + kb + g_off[p]);        \
        }                                                                      \
        asm volatile("cp.async.commit_group;");                                \
    } while (0)

    // prologue: stages 0,1
    LOAD_STAGE(0, 0);
    LOAD_STAGE(1, 1);

    float acc[2][8][4];
#pragma unroll
    for (int mi = 0; mi < 2; mi++)
#pragma unroll
        for (int ni = 0; ni < 8; ni++)
#pragma unroll
            for (int c = 0; c < 4; c++) acc[mi][ni][c] = 0.f;

    // ldmatrix per-lane base offsets
    // A: lane -> row = lane%16 (within m16 tile), colb8 = (lane/16)*16
    int a_row = lane & 15;
    int a_colb = (lane >> 4) * 16;
    // B: lane -> n row = (lane/16)*8 + lane%8 (within n16 block), k half = (lane/8)&1
    int b_row = ((lane >> 4) << 3) + (lane & 7);
    int b_colb = ((lane >> 3) & 1) * 16;

    int s = 0;
#pragma unroll 1
    for (int kit = 0; kit < KITERS; kit++) {
        asm volatile("cp.async.wait_group 1;" ::: "memory");
        __syncthreads();

        if (kit + 2 < KITERS) {
            int ls = kit + 2;
            LOAD_STAGE((s + 2) % STAGES, ls);
        }

        unsigned sAh = sb + s * STAGE_BYTES;
        unsigned sAl = sAh + TILE_BYTES;
        unsigned sB  = sAh + 2 * TILE_BYTES;

#pragma unroll
        for (int kt = 0; kt < 4; kt++) {
            unsigned bfr[8][2];
#pragma unroll
            for (int nb = 0; nb < 4; nb++) {
                int nrow = wn * 64 + nb * 16 + b_row;
                unsigned addr = sB + sw128((unsigned)(nrow * 128 + kt * 32 + b_colb));
                ldsm_x4(bfr[2 * nb][0], bfr[2 * nb][1], bfr[2 * nb + 1][0], bfr[2 * nb + 1][1], addr);
            }
            unsigned ah[2][4], al[2][4];
#pragma unroll
            for (int mi = 0; mi < 2; mi++) {
                int mrow = wm * 32 + mi * 16 + a_row;
                unsigned off = sw128((unsigned)(mrow * 128 + kt * 32 + a_colb));
                ldsm_x4(ah[mi][0], ah[mi][1], ah[mi][2], ah[mi][3], sAh + off);
                ldsm_x4(al[mi][0], al[mi][1], al[mi][2], al[mi][3], sAl + off);
            }
#pragma unroll
            for (int mi = 0; mi < 2; mi++)
#pragma unroll
                for (int ni = 0; ni < 8; ni++) {
                    mma16816(acc[mi][ni], ah[mi], bfr[ni]);
                    mma16816(acc[mi][ni], al[mi], bfr[ni]);
                }
        }
        s = (s + 1) % STAGES;
    }

    // ------------------ epilogue ------------------
    int qrow = lane >> 2;          // 0..7
    int qcol = (lane & 3) * 2;     // 0,2,4,6
#pragma unroll
    for (int mi = 0; mi < 2; mi++) {
        int r0 = m_base + wm * 32 + mi * 16 + qrow;
#pragma unroll
        for (int ni = 0; ni < 8; ni++) {
            int c = n_base + wn * 64 + ni * 8 + qcol;
            float2 bb = *reinterpret_cast<const float2*>(bias + c);
            float2 v0, v1;
            v0.x = acc[mi][ni][0] + bb.x;
            v0.y = acc[mi][ni][1] + bb.y;
            v1.x = acc[mi][ni][2] + bb.x;
            v1.y = acc[mi][ni][3] + bb.y;
            *reinterpret_cast<float2*>(out + (size_t)r0 * DIMM + c) = v0;
            *reinterpret_cast<float2*>(out + (size_t)(r0 + 8) * DIMM + c) = v1;
        }
    }
#undef LOAD_STAGE
}

// ------------------------- launch ------------------------------------------

extern "C" void kernel_launch(void* const* d_in, const int* in_sizes, int n_in,
                              void* d_out, int out_size) {
    const float* x = (const float*)d_in[0];
    const float* W = (const float*)d_in[1];
    const float* b = (const float*)d_in[2];
    float* out = (float*)d_out;

    cudaFuncSetAttribute(bgemm_kernel, cudaFuncAttributeMaxDynamicSharedMemorySize, SMEM_TOTAL);

    split_kernel<<<(DIMM * (size_t)DIMM) / 4 / 256, 256>>>(x);
    signT_kernel<<<dim3(DIMM / 32, DIMM / 32), dim3(32, 8)>>>(W);
    bgemm_kernel<<<(DIMM / BM) * (DIMM / BN), 256, SMEM_TOTAL>>>(b, out);
}